// round 11
// baseline (speedup 1.0000x reference)
#include <cuda_runtime.h>
#include <cuda_fp16.h>
#include <stdint.h>

// Problem shape: 100000 users + 50000 items, D=64, E=2M.
#define MAXN 150016
#define MAXE 2000000
#define D 64
#define ROW_U4 8               // 64 halfs = 8 uint4 (16B) per row
#define SCAN_T 1024
#define MAX_BLOCKS 256
#define NLAYERS 4

// -------- static device scratch --------
__device__ int    g_deg[MAXN];
__device__ float  g_dis[MAXN];
__device__ float  g_inv[MAXN];          // sqrt(deg), 0 if deg==0
__device__ int    g_off[MAXN + 1];
__device__ int    g_cur[MAXN];
__device__ int    g_csr[MAXE];
__device__ int    g_bsum[MAX_BLOCKS];
__device__ int    g_flag[MAX_BLOCKS];
// t_0..t_3 message buffers, fp16: t_k = dis * e_k (t4 never materialized)
__device__ __half g_t[(size_t)NLAYERS * MAXN * D];

// -------- preprocessing kernels (unchanged from R10) --------

__global__ void count_deg_kernel(const int* __restrict__ dst, int E, int N) {
    if (threadIdx.x == 0 && blockIdx.x < MAX_BLOCKS) g_flag[blockIdx.x] = 0;
    int q = blockIdx.x * blockDim.x + threadIdx.x;
    int base = q << 2;
    if (base + 3 < E) {
        int4 d4 = *(const int4*)&dst[base];
        if ((unsigned)d4.x < (unsigned)N) atomicAdd(&g_deg[d4.x], 1);
        if ((unsigned)d4.y < (unsigned)N) atomicAdd(&g_deg[d4.y], 1);
        if ((unsigned)d4.z < (unsigned)N) atomicAdd(&g_deg[d4.z], 1);
        if ((unsigned)d4.w < (unsigned)N) atomicAdd(&g_deg[d4.w], 1);
    } else {
        for (int e = base; e < E; e++) {
            int d = dst[e];
            if ((unsigned)d < (unsigned)N) atomicAdd(&g_deg[d], 1);
        }
    }
}

__global__ void __launch_bounds__(SCAN_T)
scan_fused_kernel(const float* __restrict__ emb_users,
                  const float* __restrict__ emb_items,
                  int nu_elems, int N) {
    __shared__ int wsum[32];
    __shared__ int block_prefix_s;
    int t = threadIdx.x;
    int b = blockIdx.x;
    int i = b * SCAN_T + t;
    int v = (i < N) ? g_deg[i] : 0;

    int x = v;
    #pragma unroll
    for (int off = 1; off < 32; off <<= 1) {
        int y = __shfl_up_sync(0xffffffff, x, off);
        if ((t & 31) >= off) x += y;
    }
    if ((t & 31) == 31) wsum[t >> 5] = x;
    __syncthreads();

    if (t < 32) {
        int w = wsum[t];
        #pragma unroll
        for (int off = 1; off < 32; off <<= 1) {
            int y = __shfl_up_sync(0xffffffff, w, off);
            if (t >= off) w += y;
        }
        wsum[t] = w;
    }
    __syncthreads();

    int base = (t >= 32) ? wsum[(t >> 5) - 1] : 0;
    int incl_local = base + x;
    int block_total = wsum[31];

    if (t == 0) {
        g_bsum[b] = block_total;
        __threadfence();
        atomicExch(&g_flag[b], 1);
    }
    if (t < 32) {
        int acc = 0;
        for (int pb = t; pb < b; pb += 32) {
            while (atomicAdd(&g_flag[pb], 0) == 0) { }
            acc += atomicAdd(&g_bsum[pb], 0);
        }
        #pragma unroll
        for (int off = 16; off > 0; off >>= 1)
            acc += __shfl_down_sync(0xffffffff, acc, off);
        if (t == 0) block_prefix_s = acc;
    }
    __syncthreads();
    int bp = block_prefix_s;

    if (i < N) {
        int incl = bp + incl_local;
        g_off[i + 1] = incl;
        g_cur[i]     = incl - v;
        float fd = (float)v;
        g_dis[i] = (v > 0) ? rsqrtf(fd) : 0.0f;
        g_inv[i] = (v > 0) ? sqrtf(fd) : 0.0f;
        if (i == 0) g_off[0] = 0;
    }
    __syncthreads();

    int chunk_nodes = min(SCAN_T, N - b * SCAN_T);
    if (chunk_nodes <= 0) return;
    int elems = chunk_nodes * D;
    size_t ebase = (size_t)b * SCAN_T * D;
    for (int k = t; k < elems; k += SCAN_T) {
        size_t idx = ebase + k;
        float v0 = (idx < (size_t)nu_elems) ? emb_users[idx]
                                            : emb_items[idx - nu_elems];
        g_t[idx] = __float2half(g_dis[idx >> 6] * v0);
    }
}

__global__ void scatter_kernel(const int* __restrict__ src,
                               const int* __restrict__ dst, int E, int N) {
    int q = blockIdx.x * blockDim.x + threadIdx.x;
    int base = q << 2;
    if (base + 3 < E) {
        int4 s4 = *(const int4*)&src[base];
        int4 d4 = *(const int4*)&dst[base];
        #define SC1(ss, dd) \
            if ((unsigned)(dd) < (unsigned)N && (unsigned)(ss) < (unsigned)N) { \
                int pos = atomicAdd(&g_cur[dd], 1); \
                if ((unsigned)pos < (unsigned)MAXE) g_csr[pos] = (ss); }
        SC1(s4.x, d4.x) SC1(s4.y, d4.y) SC1(s4.z, d4.z) SC1(s4.w, d4.w)
        #undef SC1
    } else {
        for (int e = base; e < E; e++) {
            int d = dst[e];
            int s = src[e];
            if ((unsigned)d < (unsigned)N && (unsigned)s < (unsigned)N) {
                int pos = atomicAdd(&g_cur[d], 1);
                if ((unsigned)pos < (unsigned)MAXE) g_csr[pos] = s;
            }
        }
    }
}

// -------- warp-per-node gather --------
// lane = grp*8 + q: grp = edge slot (4 edges/iter), q = row-eighth (16B).
// Returns fp32 sums f[0..7] = the 8 values of this lane's row-eighth,
// reduced over ALL edges of the node (valid in every lane).
__device__ __forceinline__ void gather_sum_w(const uint4* __restrict__ tin,
                                             int s, int e, int grp, int q,
                                             float* f) {
    __half2 zz = __floats2half2_rn(0.f, 0.f);
    __half2 a0 = zz, a1 = zz, a2 = zz, a3 = zz;

    int p = s;
    if (p + 3 < e) {
        int u = __ldg(&g_csr[p + grp]);
        for (;;) {
            int pn = p + 4;
            bool more = (pn + 3 < e);
            int un;
            if (more) un = __ldg(&g_csr[pn + grp]);   // prefetch next
            uint4 r = __ldg(&tin[(size_t)u * ROW_U4 + q]);
            a0 = __hadd2(a0, *(__half2*)&r.x);
            a1 = __hadd2(a1, *(__half2*)&r.y);
            a2 = __hadd2(a2, *(__half2*)&r.z);
            a3 = __hadd2(a3, *(__half2*)&r.w);
            p = pn;
            if (!more) break;
            u = un;
        }
    }
    int rem = e - p;                 // 0..3
    if (rem > 0) {
        int idx = p + grp;
        if (idx >= e) idx = e - 1;   // clamp (masked out below)
        int u = __ldg(&g_csr[idx]);
        uint4 r = __ldg(&tin[(size_t)u * ROW_U4 + q]);
        if (grp < rem) {
            a0 = __hadd2(a0, *(__half2*)&r.x);
            a1 = __hadd2(a1, *(__half2*)&r.y);
            a2 = __hadd2(a2, *(__half2*)&r.z);
            a3 = __hadd2(a3, *(__half2*)&r.w);
        }
    }

    float2 f0 = __half22float2(a0);
    float2 f1 = __half22float2(a1);
    float2 f2 = __half22float2(a2);
    float2 f3 = __half22float2(a3);
    f[0] = f0.x; f[1] = f0.y; f[2] = f1.x; f[3] = f1.y;
    f[4] = f2.x; f[5] = f2.y; f[6] = f3.x; f[7] = f3.y;

    // fp32 reduce across the 4 edge groups (lane bits 3,4)
    #pragma unroll
    for (int j = 0; j < 8; j++) {
        f[j] += __shfl_xor_sync(0xffffffff, f[j], 8);
        f[j] += __shfl_xor_sync(0xffffffff, f[j], 16);
    }
}

// Layers 1..3: read t_{k-1}, write t_k. One node per warp.
__global__ void __launch_bounds__(256)
layer_kernel(int N, int kin) {
    int gtid = blockIdx.x * blockDim.x + threadIdx.x;
    int node = gtid >> 5;
    int lane = gtid & 31;
    if (node >= N) return;
    int grp = lane >> 3;
    int q   = lane & 7;

    const uint4* __restrict__ tin =
        (const uint4*)(g_t + (size_t)kin * MAXN * D);
    uint4* __restrict__ tout =
        (uint4*)(g_t + (size_t)(kin + 1) * MAXN * D);

    float f[8];
    gather_sum_w(tin, g_off[node], g_off[node + 1], grp, q, f);

    if (grp == 0) {
        float dv = g_dis[node];
        float d2 = dv * dv;                       // t_next = dis^2 * sum
        __half2 h0 = __floats2half2_rn(d2 * f[0], d2 * f[1]);
        __half2 h1 = __floats2half2_rn(d2 * f[2], d2 * f[3]);
        __half2 h2 = __floats2half2_rn(d2 * f[4], d2 * f[5]);
        __half2 h3 = __floats2half2_rn(d2 * f[6], d2 * f[7]);
        uint4 o;
        o.x = *(uint32_t*)&h0; o.y = *(uint32_t*)&h1;
        o.z = *(uint32_t*)&h2; o.w = *(uint32_t*)&h3;
        tout[(size_t)node * ROW_U4 + q] = o;
    }
}

// Layer 4 fused with the final combine:
// out = (e0 + inv*(t1+t2+t3) + dis*sum) / 25
__global__ void __launch_bounds__(256)
layer_final_kernel(const float* __restrict__ emb_users,
                   const float* __restrict__ emb_items,
                   float* __restrict__ out, int N, int NU) {
    int gtid = blockIdx.x * blockDim.x + threadIdx.x;
    int node = gtid >> 5;
    int lane = gtid & 31;
    if (node >= N) return;
    int grp = lane >> 3;
    int q   = lane & 7;

    const uint4* __restrict__ t1 = (const uint4*)(g_t + (size_t)1 * MAXN * D);
    const uint4* __restrict__ t2 = (const uint4*)(g_t + (size_t)2 * MAXN * D);
    const uint4* __restrict__ t3 = (const uint4*)(g_t + (size_t)3 * MAXN * D);

    float f[8];
    gather_sum_w(t3, g_off[node], g_off[node + 1], grp, q, f);

    if (grp == 0) {
        size_t oidx = (size_t)node * ROW_U4 + q;
        uint4 w1 = t1[oidx];
        uint4 w2 = t2[oidx];
        uint4 w3 = t3[oidx];

        float sv[8];
        {
            float2 p1, p2, p3;
            p1 = __half22float2(*(__half2*)&w1.x);
            p2 = __half22float2(*(__half2*)&w2.x);
            p3 = __half22float2(*(__half2*)&w3.x);
            sv[0] = p1.x + p2.x + p3.x; sv[1] = p1.y + p2.y + p3.y;
            p1 = __half22float2(*(__half2*)&w1.y);
            p2 = __half22float2(*(__half2*)&w2.y);
            p3 = __half22float2(*(__half2*)&w3.y);
            sv[2] = p1.x + p2.x + p3.x; sv[3] = p1.y + p2.y + p3.y;
            p1 = __half22float2(*(__half2*)&w1.z);
            p2 = __half22float2(*(__half2*)&w2.z);
            p3 = __half22float2(*(__half2*)&w3.z);
            sv[4] = p1.x + p2.x + p3.x; sv[5] = p1.y + p2.y + p3.y;
            p1 = __half22float2(*(__half2*)&w1.w);
            p2 = __half22float2(*(__half2*)&w2.w);
            p3 = __half22float2(*(__half2*)&w3.w);
            sv[6] = p1.x + p2.x + p3.x; sv[7] = p1.y + p2.y + p3.y;
        }

        // e0: 8 contiguous fp32 at element offset node*64 + q*8
        size_t ebase = (size_t)node * D + q * 8;
        const float* esrc = (node < NU) ? (emb_users + ebase)
                                        : (emb_items + (ebase - (size_t)NU * D));
        float4 e0a = *(const float4*)(esrc);
        float4 e0b = *(const float4*)(esrc + 4);

        float dv  = g_dis[node];
        float inv = g_inv[node];
        const float sc = 1.0f / 25.0f;
        float4 ra, rb;
        ra.x = (e0a.x + inv * sv[0] + dv * f[0]) * sc;
        ra.y = (e0a.y + inv * sv[1] + dv * f[1]) * sc;
        ra.z = (e0a.z + inv * sv[2] + dv * f[2]) * sc;
        ra.w = (e0a.w + inv * sv[3] + dv * f[3]) * sc;
        rb.x = (e0b.x + inv * sv[4] + dv * f[4]) * sc;
        rb.y = (e0b.y + inv * sv[5] + dv * f[5]) * sc;
        rb.z = (e0b.z + inv * sv[6] + dv * f[6]) * sc;
        rb.w = (e0b.w + inv * sv[7] + dv * f[7]) * sc;
        *(float4*)&out[ebase]     = ra;
        *(float4*)&out[ebase + 4] = rb;
    }
}

// -------- launch --------
extern "C" void kernel_launch(void* const* d_in, const int* in_sizes, int n_in,
                              void* d_out, int out_size) {
    const float* emb_users = (const float*)d_in[0];
    const float* emb_items = (const float*)d_in[1];
    const int*   edge      = (const int*)d_in[2];   // int32

    int nu_elems = in_sizes[0];
    int ni_elems = in_sizes[1];
    int E        = in_sizes[2] / 2;
    int NU = nu_elems / D;
    int NI = ni_elems / D;
    int N  = NU + NI;

    const int* src = edge;
    const int* dst = edge + E;
    float* out = (float*)d_out;

    const int T = 256;
    int nScanBlocks = (N + SCAN_T - 1) / SCAN_T;   // 147 <= 148 SMs

    void* deg_ptr = nullptr;
    cudaGetSymbolAddress(&deg_ptr, g_deg);
    cudaMemsetAsync(deg_ptr, 0, (size_t)N * sizeof(int));

    int quads = (E + 3) / 4;
    count_deg_kernel<<<(quads + T - 1) / T, T>>>(dst, E, N);
    scan_fused_kernel<<<nScanBlocks, SCAN_T>>>(emb_users, emb_items, nu_elems, N);
    scatter_kernel<<<(quads + T - 1) / T, T>>>(src, dst, E, N);

    int layer_blocks = (N * 32 + T - 1) / T;   // warp per node
    layer_kernel<<<layer_blocks, T>>>(N, 0);   // t0 -> t1
    layer_kernel<<<layer_blocks, T>>>(N, 1);   // t1 -> t2
    layer_kernel<<<layer_blocks, T>>>(N, 2);   // t2 -> t3
    layer_final_kernel<<<layer_blocks, T>>>(emb_users, emb_items, out, N, NU);
}

// round 12
// speedup vs baseline: 1.3055x; 1.3055x over previous
#include <cuda_runtime.h>
#include <cuda_fp16.h>
#include <stdint.h>

// Problem shape: 100000 users + 50000 items, D=64, E=2M.
#define MAXN 150016
#define MAXE_PAD 2600000       // 2M edges + up to 3 pad slots per node
#define D 64
#define ROW_U2 16              // 64 halfs = 16 uint2 per row
#define SCAN_T 1024
#define MAX_BLOCKS 256
#define NLAYERS 4

// -------- static device scratch --------
__device__ int    g_deg[MAXN];
__device__ float  g_dis[MAXN];
__device__ float  g_inv[MAXN];          // sqrt(deg), 0 if deg==0
__device__ int    g_off[MAXN + 1];      // PADDED offsets (multiples of 4)
__device__ int    g_cur[MAXN];
__device__ int    g_csr[MAXE_PAD];
__device__ int    g_bsum[MAX_BLOCKS];
__device__ int    g_flag[MAX_BLOCKS];
// t_0..t_3 message buffers, fp16: t_k = dis * e_k (t4 never materialized)
__device__ __half g_t[(size_t)NLAYERS * MAXN * D];

// -------- preprocessing kernels --------

__global__ void count_deg_kernel(const int* __restrict__ dst, int E, int N) {
    if (threadIdx.x == 0 && blockIdx.x < MAX_BLOCKS) g_flag[blockIdx.x] = 0;
    int q = blockIdx.x * blockDim.x + threadIdx.x;
    int base = q << 2;
    if (base + 3 < E) {
        int4 d4 = *(const int4*)&dst[base];
        if ((unsigned)d4.x < (unsigned)N) atomicAdd(&g_deg[d4.x], 1);
        if ((unsigned)d4.y < (unsigned)N) atomicAdd(&g_deg[d4.y], 1);
        if ((unsigned)d4.z < (unsigned)N) atomicAdd(&g_deg[d4.z], 1);
        if ((unsigned)d4.w < (unsigned)N) atomicAdd(&g_deg[d4.w], 1);
    } else {
        for (int e = base; e < E; e++) {
            int d = dst[e];
            if ((unsigned)d < (unsigned)N) atomicAdd(&g_deg[d], 1);
        }
    }
}

// Single-pass scan of PADDED degrees + finalize + t0 init + dummy-row zeroing.
__global__ void __launch_bounds__(SCAN_T)
scan_fused_kernel(const float* __restrict__ emb_users,
                  const float* __restrict__ emb_items,
                  int nu_elems, int N) {
    __shared__ int wsum[32];
    __shared__ int block_prefix_s;
    int t = threadIdx.x;
    int b = blockIdx.x;
    int i = b * SCAN_T + t;
    int v = (i < N) ? g_deg[i] : 0;
    int pv = (v + 3) & ~3;                 // padded degree

    int x = pv;
    #pragma unroll
    for (int off = 1; off < 32; off <<= 1) {
        int y = __shfl_up_sync(0xffffffff, x, off);
        if ((t & 31) >= off) x += y;
    }
    if ((t & 31) == 31) wsum[t >> 5] = x;
    __syncthreads();

    if (t < 32) {
        int w = wsum[t];
        #pragma unroll
        for (int off = 1; off < 32; off <<= 1) {
            int y = __shfl_up_sync(0xffffffff, w, off);
            if (t >= off) w += y;
        }
        wsum[t] = w;
    }
    __syncthreads();

    int base = (t >= 32) ? wsum[(t >> 5) - 1] : 0;
    int incl_local = base + x;
    int block_total = wsum[31];

    if (t == 0) {
        g_bsum[b] = block_total;
        __threadfence();
        atomicExch(&g_flag[b], 1);
    }
    if (t < 32) {
        int acc = 0;
        for (int pb = t; pb < b; pb += 32) {
            while (atomicAdd(&g_flag[pb], 0) == 0) { }
            acc += atomicAdd(&g_bsum[pb], 0);
        }
        #pragma unroll
        for (int off = 16; off > 0; off >>= 1)
            acc += __shfl_down_sync(0xffffffff, acc, off);
        if (t == 0) block_prefix_s = acc;
    }
    __syncthreads();
    int bp = block_prefix_s;

    if (i < N) {
        int incl = bp + incl_local;        // padded inclusive
        g_off[i + 1] = incl;
        g_cur[i]     = incl - pv;          // padded start
        float fd = (float)v;
        g_dis[i] = (v > 0) ? rsqrtf(fd) : 0.0f;
        g_inv[i] = (v > 0) ? sqrtf(fd) : 0.0f;
        if (i == 0) g_off[0] = 0;
    }
    __syncthreads();

    // zero the DUMMY node's row (node id = N) in all 4 t buffers (block 0 only)
    if (b == 0 && t < (NLAYERS * D) / 2) {
        int buf = t / (D / 2);
        int j   = t % (D / 2);
        ((uint32_t*)(g_t + (size_t)buf * MAXN * D + (size_t)N * D))[j] = 0;
    }

    // t0 init for this block's node chunk
    int chunk_nodes = min(SCAN_T, N - b * SCAN_T);
    if (chunk_nodes <= 0) return;
    int elems = chunk_nodes * D;
    size_t ebase = (size_t)b * SCAN_T * D;
    for (int k = t; k < elems; k += SCAN_T) {
        size_t idx = ebase + k;
        float v0 = (idx < (size_t)nu_elems) ? emb_users[idx]
                                            : emb_items[idx - nu_elems];
        g_t[idx] = __float2half(g_dis[idx >> 6] * v0);
    }
}

__global__ void scatter_kernel(const int* __restrict__ src,
                               const int* __restrict__ dst, int E, int N) {
    int q = blockIdx.x * blockDim.x + threadIdx.x;
    int base = q << 2;
    if (base + 3 < E) {
        int4 s4 = *(const int4*)&src[base];
        int4 d4 = *(const int4*)&dst[base];
        #define SC1(ss, dd) \
            if ((unsigned)(dd) < (unsigned)N && (unsigned)(ss) < (unsigned)N) { \
                int pos = atomicAdd(&g_cur[dd], 1); \
                if ((unsigned)pos < (unsigned)MAXE_PAD) g_csr[pos] = (ss); }
        SC1(s4.x, d4.x) SC1(s4.y, d4.y) SC1(s4.z, d4.z) SC1(s4.w, d4.w)
        #undef SC1
    } else {
        for (int e = base; e < E; e++) {
            int d = dst[e];
            int s = src[e];
            if ((unsigned)d < (unsigned)N && (unsigned)s < (unsigned)N) {
                int pos = atomicAdd(&g_cur[d], 1);
                if ((unsigned)pos < (unsigned)MAXE_PAD) g_csr[pos] = s;
            }
        }
    }
}

// Fill the pad slots of each node's list with the dummy node id N.
__global__ void pad_fill_kernel(int N) {
    int i = blockIdx.x * blockDim.x + threadIdx.x;
    if (i < N) {
        int p = g_cur[i];            // end of real edges
        int e = g_off[i + 1];        // padded end
        for (; p < e; p++) g_csr[p] = N;
    }
}

// Gather: padded lists -> single 4-unrolled pipelined loop, no head/tail.
__device__ __forceinline__ void gather_sum(const uint2* __restrict__ tin,
                                           int s, int e, int sub,
                                           float& ax, float& ay,
                                           float& az, float& aw) {
    ax = ay = az = aw = 0.f;
    if (s >= e) return;
    int4 u = *(const int4*)&g_csr[s];
    int p = s;
    for (;;) {
        int pn = p + 4;
        bool more = pn < e;
        int4 un;
        if (more) un = *(const int4*)&g_csr[pn];   // prefetch next quad
        uint2 r0 = __ldg(&tin[(size_t)u.x * ROW_U2 + sub]);
        uint2 r1 = __ldg(&tin[(size_t)u.y * ROW_U2 + sub]);
        uint2 r2 = __ldg(&tin[(size_t)u.z * ROW_U2 + sub]);
        uint2 r3 = __ldg(&tin[(size_t)u.w * ROW_U2 + sub]);
        __half2 lo01 = __hadd2(*(__half2*)&r0.x, *(__half2*)&r1.x);
        __half2 lo23 = __hadd2(*(__half2*)&r2.x, *(__half2*)&r3.x);
        __half2 hi01 = __hadd2(*(__half2*)&r0.y, *(__half2*)&r1.y);
        __half2 hi23 = __hadd2(*(__half2*)&r2.y, *(__half2*)&r3.y);
        float2 fl = __half22float2(__hadd2(lo01, lo23));
        float2 fh = __half22float2(__hadd2(hi01, hi23));
        ax += fl.x; ay += fl.y; az += fh.x; aw += fh.y;
        if (!more) break;
        p = pn;
        u = un;
    }
}

// Layers 1..3: read t_{k-1}, write t_k. Two nodes per warp, 8B per lane.
__global__ void __launch_bounds__(256)
layer_kernel(int N, int kin) {
    int gtid = blockIdx.x * blockDim.x + threadIdx.x;
    int w    = gtid >> 5;
    int lane = gtid & 31;
    int node = (w << 1) | (lane >> 4);
    int sub  = lane & 15;
    if (node >= N) return;

    const uint2* __restrict__ tin =
        (const uint2*)(g_t + (size_t)kin * MAXN * D);
    uint2* __restrict__ tout =
        (uint2*)(g_t + (size_t)(kin + 1) * MAXN * D);

    float ax, ay, az, aw;
    gather_sum(tin, g_off[node], g_off[node + 1], sub, ax, ay, az, aw);

    float dv = g_dis[node];
    float d2 = dv * dv;          // t_next = dis^2 * sum
    uint2 o;
    __half2 lo = __floats2half2_rn(d2 * ax, d2 * ay);
    __half2 hi = __floats2half2_rn(d2 * az, d2 * aw);
    o.x = *(uint32_t*)&lo;
    o.y = *(uint32_t*)&hi;
    tout[(size_t)node * ROW_U2 + sub] = o;
}

// Layer 4 fused with the final combine:
// out = (e0 + inv*(t1+t2+t3) + dis*sum) / 25
__global__ void __launch_bounds__(256)
layer_final_kernel(const float* __restrict__ emb_users,
                   const float* __restrict__ emb_items,
                   float* __restrict__ out, int N, int NU) {
    int gtid = blockIdx.x * blockDim.x + threadIdx.x;
    int w    = gtid >> 5;
    int lane = gtid & 31;
    int node = (w << 1) | (lane >> 4);
    int sub  = lane & 15;
    if (node >= N) return;

    const uint2* __restrict__ t1 = (const uint2*)(g_t + (size_t)1 * MAXN * D);
    const uint2* __restrict__ t2 = (const uint2*)(g_t + (size_t)2 * MAXN * D);
    const uint2* __restrict__ t3 = (const uint2*)(g_t + (size_t)3 * MAXN * D);

    float ax, ay, az, aw;
    gather_sum(t3, g_off[node], g_off[node + 1], sub, ax, ay, az, aw);

    size_t oidx = (size_t)node * ROW_U2 + sub;
    uint2 w1 = t1[oidx];
    uint2 w2 = t2[oidx];
    uint2 w3 = t3[oidx];

    float2 f1a = __half22float2(*(__half2*)&w1.x);
    float2 f1b = __half22float2(*(__half2*)&w1.y);
    float2 f2a = __half22float2(*(__half2*)&w2.x);
    float2 f2b = __half22float2(*(__half2*)&w2.y);
    float2 f3a = __half22float2(*(__half2*)&w3.x);
    float2 f3b = __half22float2(*(__half2*)&w3.y);

    float sx = f1a.x + f2a.x + f3a.x;
    float sy = f1a.y + f2a.y + f3a.y;
    float sz = f1b.x + f2b.x + f3b.x;
    float sw = f1b.y + f2b.y + f3b.y;

    size_t ebase = (size_t)node * D + sub * 4;
    float4 e0;
    if (node < NU) {
        e0 = *(const float4*)&emb_users[ebase];
    } else {
        e0 = *(const float4*)&emb_items[ebase - (size_t)NU * D];
    }

    float dv  = g_dis[node];
    float inv = g_inv[node];
    const float sc = 1.0f / 25.0f;
    float4 r;
    r.x = (e0.x + inv * sx + dv * ax) * sc;
    r.y = (e0.y + inv * sy + dv * ay) * sc;
    r.z = (e0.z + inv * sz + dv * az) * sc;
    r.w = (e0.w + inv * sw + dv * aw) * sc;
    *(float4*)&out[ebase] = r;
}

// -------- launch --------
extern "C" void kernel_launch(void* const* d_in, const int* in_sizes, int n_in,
                              void* d_out, int out_size) {
    const float* emb_users = (const float*)d_in[0];
    const float* emb_items = (const float*)d_in[1];
    const int*   edge      = (const int*)d_in[2];   // int32

    int nu_elems = in_sizes[0];
    int ni_elems = in_sizes[1];
    int E        = in_sizes[2] / 2;
    int NU = nu_elems / D;
    int NI = ni_elems / D;
    int N  = NU + NI;

    const int* src = edge;
    const int* dst = edge + E;
    float* out = (float*)d_out;

    const int T = 256;
    int nScanBlocks = (N + SCAN_T - 1) / SCAN_T;   // 147 <= 148 SMs

    void* deg_ptr = nullptr;
    cudaGetSymbolAddress(&deg_ptr, g_deg);
    cudaMemsetAsync(deg_ptr, 0, (size_t)N * sizeof(int));

    int quads = (E + 3) / 4;
    count_deg_kernel<<<(quads + T - 1) / T, T>>>(dst, E, N);
    scan_fused_kernel<<<nScanBlocks, SCAN_T>>>(emb_users, emb_items, nu_elems, N);
    scatter_kernel<<<(quads + T - 1) / T, T>>>(src, dst, E, N);
    pad_fill_kernel<<<(N + T - 1) / T, T>>>(N);

    int layer_blocks = (N * 16 + T - 1) / T;   // 2 nodes per warp
    layer_kernel<<<layer_blocks, T>>>(N, 0);   // t0 -> t1
    layer_kernel<<<layer_blocks, T>>>(N, 1);   // t1 -> t2
    layer_kernel<<<layer_blocks, T>>>(N, 2);   // t2 -> t3
    layer_final_kernel<<<layer_blocks, T>>>(emb_users, emb_items, out, N, NU);
}